// round 1
// baseline (speedup 1.0000x reference)
#include <cuda_runtime.h>

// One thread computes one batch's 64-point inverse DFT (radix 8x8 Cooley-Tukey).
// Shared memory staging gives fully coalesced global loads/stores; padded row
// stride (132 floats) makes the per-thread strided row access conflict-free.

#define NT     64            // threads per block == batches per block
#define ROWF   132           // padded row stride in floats (128 data + 4 pad)
#define TWOFF  (NT * ROWF)   // twiddle table offset (floats)
#define SMEMF  (TWOFF + 104) // 50 float2 twiddles + pad

__device__ __forceinline__ void ifft8(float* tr, float* ti) {
    // 8-point DFT with POSITIVE exponent: y[m] = sum_t u[t] e^{+j 2 pi m t / 8}
    float e0r = tr[0] + tr[4], e0i = ti[0] + ti[4];
    float e1r = tr[0] - tr[4], e1i = ti[0] - ti[4];
    float e2r = tr[2] + tr[6], e2i = ti[2] + ti[6];
    float e3r = tr[2] - tr[6], e3i = ti[2] - ti[6];
    float E0r = e0r + e2r,  E0i = e0i + e2i;
    float E2r = e0r - e2r,  E2i = e0i - e2i;
    float E1r = e1r - e3i,  E1i = e1i + e3r;   // e1 + j*e3
    float E3r = e1r + e3i,  E3i = e1i - e3r;   // e1 - j*e3

    float o0r = tr[1] + tr[5], o0i = ti[1] + ti[5];
    float o1r = tr[1] - tr[5], o1i = ti[1] - ti[5];
    float o2r = tr[3] + tr[7], o2i = ti[3] + ti[7];
    float o3r = tr[3] - tr[7], o3i = ti[3] - ti[7];
    float O0r = o0r + o2r,  O0i = o0i + o2i;
    float O2r = o0r - o2r,  O2i = o0i - o2i;
    float O1r = o1r - o3i,  O1i = o1i + o3r;
    float O3r = o1r + o3i,  O3i = o1i - o3r;

    const float R = 0.70710678118654752f;      // sqrt(2)/2
    float t1r =  R * (O1r - O1i), t1i =  R * (O1r + O1i);  // W8^1 * O1
    float t2r = -O2i,             t2i =  O2r;              // j * O2
    float t3r = -R * (O3r + O3i), t3i =  R * (O3r - O3i);  // W8^3 * O3

    tr[0] = E0r + O0r;  ti[0] = E0i + O0i;
    tr[4] = E0r - O0r;  ti[4] = E0i - O0i;
    tr[1] = E1r + t1r;  ti[1] = E1i + t1i;
    tr[5] = E1r - t1r;  ti[5] = E1i - t1i;
    tr[2] = E2r + t2r;  ti[2] = E2i + t2i;
    tr[6] = E2r - t2r;  ti[6] = E2i - t2i;
    tr[3] = E3r + t3r;  ti[3] = E3i + t3i;
    tr[7] = E3r - t3r;  ti[7] = E3i - t3i;
}

__global__ void __launch_bounds__(NT)
ofdm_ifft64_kernel(const float4* __restrict__ gin, float4* __restrict__ gout) {
    __shared__ float smem[SMEMF];
    const int tid = threadIdx.x;
    const int bid = blockIdx.x;

    // Stage-2 twiddle table, indexed by p = n1*k2 (0..49):
    // T(p) = e^{+j pi p / 32} * (1/64)   (overall 1/N scale folded in)
    if (tid < 50) {
        float s, c;
        sincospif((float)tid * (1.0f / 32.0f), &s, &c);
        ((float2*)(smem + TWOFF))[tid] = make_float2(c * 0.015625f, s * 0.015625f);
    }

    // Coalesced global -> smem staging (64 rows x 32 float4 per block)
    const float4* src = gin + (size_t)bid * (NT * 32);
    #pragma unroll
    for (int i = 0; i < 32; i++) {
        int idx = tid + i * NT;
        int row = idx >> 5, col = idx & 31;
        *(float4*)(smem + row * ROWF + col * 4) = src[idx];
    }
    __syncthreads();

    float* myrow = smem + tid * ROWF;
    float xr[64], xi[64];
    #pragma unroll
    for (int i = 0; i < 16; i++) {
        float4 v = *(const float4*)(myrow + 4 * i);
        xr[4*i] = v.x; xr[4*i+1] = v.y; xr[4*i+2] = v.z; xr[4*i+3] = v.w;
    }
    #pragma unroll
    for (int i = 0; i < 16; i++) {
        float4 v = *(const float4*)(myrow + 64 + 4 * i);
        xi[4*i] = v.x; xi[4*i+1] = v.y; xi[4*i+2] = v.z; xi[4*i+3] = v.w;
    }

    // Pilot overrides
    xr[11] = 1.0f; xi[11] = 0.0f;
    xr[25] = 1.0f; xi[25] = 0.0f;
    xr[39] = 1.0f; xi[39] = 0.0f;
    xr[53] = 1.0f; xi[53] = 0.0f;

    // ---- Stage 1: 8 IDFT-8s over k1 (stride-8 gathers), A[k2][n1] -> idx 8*n1+k2
    #pragma unroll
    for (int k2 = 0; k2 < 8; k2++) {
        float tr[8], ti[8];
        #pragma unroll
        for (int k1 = 0; k1 < 8; k1++) { tr[k1] = xr[8*k1 + k2]; ti[k1] = xi[8*k1 + k2]; }
        ifft8(tr, ti);
        #pragma unroll
        for (int n1 = 0; n1 < 8; n1++) { xr[8*n1 + k2] = tr[n1]; xi[8*n1 + k2] = ti[n1]; }
    }

    // ---- Twiddle (+ 1/64 scale): element (n1,k2) *= T(n1*k2), uniform smem broadcast
    const float2* tw = (const float2*)(smem + TWOFF);
    #pragma unroll
    for (int n1 = 0; n1 < 8; n1++) {
        #pragma unroll
        for (int k2 = 0; k2 < 8; k2++) {
            int idx = 8*n1 + k2;
            float2 t = tw[n1 * k2];
            float a = xr[idx], b = xi[idx];
            xr[idx] = a * t.x - b * t.y;
            xi[idx] = a * t.y + b * t.x;
        }
    }

    // ---- Stage 2: 8 IDFT-8s over k2 (contiguous rows), X[n1 + 8*n2]
    float yr[64], yi[64];
    #pragma unroll
    for (int n1 = 0; n1 < 8; n1++) {
        float tr[8], ti[8];
        #pragma unroll
        for (int k2 = 0; k2 < 8; k2++) { tr[k2] = xr[8*n1 + k2]; ti[k2] = xi[8*n1 + k2]; }
        ifft8(tr, ti);
        #pragma unroll
        for (int n2 = 0; n2 < 8; n2++) { yr[n1 + 8*n2] = tr[n2]; yi[n1 + 8*n2] = ti[n2]; }
    }

    // Vectorized write back into own smem row (input fully consumed)
    #pragma unroll
    for (int i = 0; i < 16; i++)
        *(float4*)(myrow + 4 * i)      = make_float4(yr[4*i], yr[4*i+1], yr[4*i+2], yr[4*i+3]);
    #pragma unroll
    for (int i = 0; i < 16; i++)
        *(float4*)(myrow + 64 + 4 * i) = make_float4(yi[4*i], yi[4*i+1], yi[4*i+2], yi[4*i+3]);

    __syncthreads();

    // Coalesced smem -> global store
    float4* dst = gout + (size_t)bid * (NT * 32);
    #pragma unroll
    for (int i = 0; i < 32; i++) {
        int idx = tid + i * NT;
        int row = idx >> 5, col = idx & 31;
        dst[idx] = *(const float4*)(smem + row * ROWF + col * 4);
    }
}

extern "C" void kernel_launch(void* const* d_in, const int* in_sizes, int n_in,
                              void* d_out, int out_size) {
    const float4* gin = (const float4*)d_in[0];   // eq_freq [B,2,64] f32
    float4* gout = (float4*)d_out;                // out      [B,2,64] f32
    int batches = in_sizes[0] / 128;              // 262144
    int grid = batches / NT;                      // 4096
    ofdm_ifft64_kernel<<<grid, NT>>>(gin, gout);
}